// round 14
// baseline (speedup 1.0000x reference)
#include <cuda_runtime.h>
#include <cuda_bf16.h>
#include <cstdint>

// ============================================================================
// Problem constants: B=64, K=24, D=8, n=64 obj, 4096 pairs/batch, IN=52
// ============================================================================
static constexpr int NB   = 64;
static constexpr int NOBJ = 64;
static constexpr int HID  = 256;
static constexpr int NOUT = 28;
static constexpr int NTILES = 4096;     // 64 batches x 64 tiles of 64 rows
static constexpr int GRID_MAIN = 512;   // persistent CTAs (>= 2/SM resident)

// ============================================================================
// PTX helpers: ldmatrix + mma.sync + cp.async (sm_80-era, valid on sm_100)
// ============================================================================
__device__ __forceinline__ uint32_t smem_to_u32(const void* smem_ptr) {
    uint32_t addr;
    asm("{ .reg .u64 tmp; cvta.to.shared.u64 tmp, %1; cvt.u32.u64 %0, tmp; }"
        : "=r"(addr) : "l"(smem_ptr));
    return addr;
}

#define LDSM_X4(r0, r1, r2, r3, addr) \
    asm volatile("ldmatrix.sync.aligned.m8n8.x4.shared.b16 {%0,%1,%2,%3}, [%4];" \
                 : "=r"(r0), "=r"(r1), "=r"(r2), "=r"(r3) : "r"(addr))

#define MMA16816(d0, d1, d2, d3, a0, a1, a2, a3, b0, b1) \
    asm volatile("mma.sync.aligned.m16n8k16.row.col.f32.bf16.bf16.f32 " \
                 "{%0,%1,%2,%3}, {%4,%5,%6,%7}, {%8,%9}, {%0,%1,%2,%3};" \
                 : "+f"(d0), "+f"(d1), "+f"(d2), "+f"(d3) \
                 : "r"(a0), "r"(a1), "r"(a2), "r"(a3), "r"(b0), "r"(b1))

#define CP_ASYNC16(dst_u32, src_ptr) \
    asm volatile("cp.async.cg.shared.global [%0], [%1], 16;" \
                 :: "r"(dst_u32), "l"(src_ptr))

#define CP_ASYNC_COMMIT() asm volatile("cp.async.commit_group;" ::: "memory")
#define CP_ASYNC_WAIT(n)  asm volatile("cp.async.wait_group %0;" :: "n"(n) : "memory")

// ============================================================================
// Device-global scratch (no dynamic allocation allowed)
// ============================================================================
__device__ __align__(16) float g_A[NB * NOBJ * HID];
__device__ __align__(16) float g_C[NB * NOBJ * HID];
__device__ __align__(16) float g_qbias[NB * HID];
__device__ float g_xg[NB * HID];
__device__ int   g_tile_ctr;
__device__ int   g_done_ctr;
// chunked layout: [ci = layer*4 + kchunk][out 0..255][k 0..63] bf16
__device__ __align__(16) __nv_bfloat16 g_Wbf[4 * HID * HID];

// ============================================================================
// K_PREP (1024 blocks, 256 threads):
//  blocks [0,512):    A/C precompute (8 objects/block, coalesced Wg1 staging)
//  blocks [512,768):  qbias (4 blocks per batch, 64 rows each)
//  blocks [768,1024): weight convert fp32->bf16 (4 elems/thread) + zero g_xg
// ============================================================================
static constexpr int PREP_DSM = 2 * 26 * 257 * 4;   // 53456 B

__global__ void k_prep(const float* __restrict__ x,   const float* __restrict__ Wg1,
                       const float* __restrict__ qst, const float* __restrict__ Wh1,
                       const float* __restrict__ bh1, const float* __restrict__ Wg2,
                       const float* __restrict__ Wg3, const float* __restrict__ Wg4) {
    extern __shared__ float dsm[];
    __shared__ float feat[8][26];
    __shared__ float qs[256];
    int bid = blockIdx.x;
    int t   = threadIdx.x;

    if (bid < 512) {
        // ---- A/C precompute: 8 object-groups of 8 per batch ----
        float* s_wA = dsm;                 // [26][257], bank = i+o (conflict-free)
        float* s_wC = dsm + 26 * 257;
        int ab = bid >> 3;
        int jg = bid & 7;

        if (t < 8 * 26) {
            int jj = t / 26, i = t % 26;
            int j = jg * 8 + jj;
            int r = j >> 3, c = j & 7;
            float v;
            if (i < 24)       v = x[((ab * 24 + i) * 8 + r) * 8 + c];
            else if (i == 24) v = c * (8.0f / 7.0f) - 4.0f;
            else              v = r * (8.0f / 7.0f) - 4.0f;
            feat[jj][i] = v;
        }
        // coalesced linear load of Wg1 [256 out x 52 in], high MLP
#pragma unroll 13
        for (int j = t; j < 256 * 52; j += 256) {
            int o = j / 52, i = j % 52;
            float v = Wg1[j];
            if (i < 26) s_wA[i * 257 + o] = v;
            else        s_wC[(i - 26) * 257 + o] = v;
        }
        __syncthreads();

        int o = t;
#pragma unroll
        for (int jj = 0; jj < 8; jj++) {
            float sa = 0.0f, sc = 0.0f;
#pragma unroll
            for (int i = 0; i < 26; i++) {
                float f = feat[jj][i];
                sa += s_wA[i * 257 + o] * f;
                sc += s_wC[i * 257 + o] * f;
            }
            int j = jg * 8 + jj;
            g_A[(ab * NOBJ + j) * HID + o] = sa;
            g_C[(ab * NOBJ + j) * HID + o] = sc;
        }
    } else if (bid < 768) {
        // ---- qbias: 4 blocks per batch, 64 rows each, warp-per-row ----
        int idx = bid - 512;
        int qb = idx >> 2;           // batch
        int og = idx & 3;            // 64-row group
        int w = t >> 5, lane = t & 31;
        qs[t] = qst[qb * 256 + t];
        __syncthreads();
#pragma unroll 1
        for (int oi = 0; oi < 8; oi++) {
            int o = og * 64 + w * 8 + oi;
            const float* wr = Wh1 + o * 512 + 256;
            float s = 0.0f;
#pragma unroll
            for (int k = 0; k < 8; k++) s += wr[lane + 32 * k] * qs[lane + 32 * k];
#pragma unroll
            for (int sh = 16; sh; sh >>= 1) s += __shfl_xor_sync(0xFFFFFFFFu, s, sh);
            if (lane == 0) g_qbias[qb * 256 + o] = s + bh1[o];
        }
    } else {
        // ---- weight convert, 4 elems per thread; also zero g_xg / counters ----
        int base = (bid - 768) * 1024 + t;
#pragma unroll
        for (int k = 0; k < 4; k++) {
            int idx = base + k * 256;
            if (idx == 0) { g_tile_ctr = 0; g_done_ctr = 0; }
            if (idx < NB * HID) g_xg[idx] = 0.0f;
            int layer = idx >> 16, e = idx & 65535;
            int o = e >> 8, i = e & 255;
            float v;
            if (layer == 0)      v = Wg2[e];
            else if (layer == 1) v = Wg3[e];
            else if (layer == 2) v = Wg4[e];
            else                 v = Wh1[o * 512 + i];
            int c = i >> 6, kk = i & 63;
            g_Wbf[(((layer * 4 + c) * 256 + o) << 6) + kk] = __float2bfloat16(v);
        }
    }
}

// ============================================================================
// K4: fused RN core + fused f-MLP/log_softmax tail.
// Persistent CTAs (512), 128 threads (4 warps), 64 rows/tile, 2 CTAs/SM.
// After the tile loop each CTA bumps g_done_ctr; the last 64 CTAs each run
// one batch's f-MLP once the counter drains.
// ============================================================================
static constexpr int ACT_STRIDE_B = 528;
static constexpr int ACT_STRIDE_H = 264;
static constexpr int WCH_STRIDE_B = 144;
static constexpr int SMEM_ACT  = 0;                             // 64*528 = 33792
static constexpr int SMEM_W0   = 33792;
static constexpr int SMEM_W1   = SMEM_W0 + 256 * WCH_STRIDE_B;  // 70656
static constexpr int SMEM_BIAS = SMEM_W1 + 256 * WCH_STRIDE_B;  // 107520
static constexpr int SMEM_RACC = SMEM_BIAS + 1024;              // 108544
static constexpr int SMEM_MAIN_SZ = SMEM_RACC + 1024;           // 109568

// Stage this warp's 64-row slice (8 KB) of global chunk ci into buffer buf_sel.
__device__ __forceinline__ void stage_slice_warp(uint32_t smem_base, int buf_sel,
                                                 int ci, int wid, int lane) {
    const char* src = (const char*)g_Wbf + (size_t)ci * 32768 + (size_t)wid * 8192;
    uint32_t dstb = smem_base + (buf_sel ? SMEM_W1 : SMEM_W0) + wid * 64 * WCH_STRIDE_B;
#pragma unroll
    for (int i = 0; i < 16; i++) {
        int idx = i * 32 + lane;          // 16B unit, 512 per warp slice
        int row = idx >> 3;               // 8 x 16B per 128B source row
        int col = idx & 7;
        CP_ASYNC16(dstb + row * WCH_STRIDE_B + col * 16, src + idx * 16);
    }
    CP_ASYNC_COMMIT();
}

__global__ void __launch_bounds__(128, 2)
k_main(const float* __restrict__ bg1, const float* __restrict__ bg2,
       const float* __restrict__ bg3, const float* __restrict__ bg4,
       const float* __restrict__ Wf1, const float* __restrict__ bf1v,
       const float* __restrict__ Wf2, const float* __restrict__ bf2v,
       const float* __restrict__ Wf3, const float* __restrict__ bf3v,
       float* __restrict__ out) {
    extern __shared__ char smem[];
    __shared__ int s_tile;
    __shared__ int s_done;
    __shared__ float s_lg[NOUT];
    __shared__ float s_lse;
    const uint32_t smem_base = smem_to_u32(smem);

    __nv_bfloat16* s_act = (__nv_bfloat16*)(smem + SMEM_ACT);
    float* s_bias = (float*)(smem + SMEM_BIAS);
    float* s_acc  = (float*)(smem + SMEM_RACC);

    int tid  = threadIdx.x;
    int wid  = tid >> 5;
    int lane = tid & 31;
    int nbase = wid * 64;

    // fragment addresses (tile-invariant)
    uint32_t a_ptr[4];
#pragma unroll
    for (int mt = 0; mt < 4; mt++) {
        int rr = mt * 16 + (lane & 15);
        a_ptr[mt] = smem_base + SMEM_ACT + rr * ACT_STRIDE_B + (lane >> 4) * 16;
    }
    uint32_t b_off[4];
#pragma unroll
    for (int t4 = 0; t4 < 4; t4++) {
        int rr = nbase + t4 * 16 + ((lane >> 4) << 3) + (lane & 7);
        b_off[t4] = rr * WCH_STRIDE_B + ((lane >> 3) & 1) * 16;
    }

    // prologue: prefetch chunks 0 and 1 (this warp's slices)
    stage_slice_warp(smem_base, 0, 0, wid, lane);
    stage_slice_warp(smem_base, 1, 1, wid, lane);

    int ci = 0;   // persistent global chunk counter; ci & 15 = chunk id

#pragma unroll 1
    while (true) {
        if (tid == 0) s_tile = atomicAdd(&g_tile_ctr, 1);
        __syncthreads();
        int tile = s_tile;
        if (tile >= NTILES) break;
        int b    = tile >> 6;
        int row0 = (tile & 63) << 6;

        s_acc[tid] = 0.0f;
        s_acc[tid + 128] = 0.0f;

        // ---- layer 1: act = relu(A[b,q] + C[b,p] + bg1), bf16, 64 rows ----
        {
            int r = tid >> 1;
            int half = tid & 1;
            int rowg = row0 + r;
            int p = rowg >> 6, q = rowg & 63;
            const float2* A2 = (const float2*)(g_A + ((b << 6) + q) * HID + half * 128);
            const float2* C2 = (const float2*)(g_C + ((b << 6) + p) * HID + half * 128);
            const float2* B2 = (const float2*)(bg1 + half * 128);
            uint32_t* dst = (uint32_t*)(s_act + r * ACT_STRIDE_H + half * 128);
#pragma unroll
            for (int c = 0; c < 64; c++) {
                float2 av = A2[c], cv = C2[c], bv = B2[c];
                float f0 = fmaxf(av.x + cv.x + bv.x, 0.0f);
                float f1 = fmaxf(av.y + cv.y + bv.y, 0.0f);
                uint32_t lo = (uint32_t)__bfloat16_as_ushort(__float2bfloat16(f0));
                uint32_t hi = (uint32_t)__bfloat16_as_ushort(__float2bfloat16(f1));
                dst[c] = lo | (hi << 16);
            }
        }
        __syncthreads();

        // ---- layers 2..5: 16 chunks, warp-private double buffering ----
#pragma unroll 1
        for (int L = 0; L < 4; L++) {
            const float* bp = (L == 0) ? bg2 : (L == 1) ? bg3 : (L == 2) ? bg4
                                             : (const float*)(g_qbias + b * 256);
            s_bias[tid] = bp[tid];
            s_bias[tid + 128] = bp[tid + 128];

            float acc[4][8][4];
#pragma unroll
            for (int mt = 0; mt < 4; mt++)
#pragma unroll
                for (int nt = 0; nt < 8; nt++)
#pragma unroll
                    for (int j = 0; j < 4; j++) acc[mt][nt][j] = 0.0f;

#pragma unroll 1
            for (int c = 0; c < 4; c++) {
                CP_ASYNC_WAIT(1);
                __syncwarp();
                uint32_t wb = smem_base + ((ci & 1) ? SMEM_W1 : SMEM_W0);
#pragma unroll
                for (int ks = 0; ks < 4; ks++) {
                    int kk = c * 4 + ks;
                    uint32_t af[4][4];
#pragma unroll
                    for (int mt = 0; mt < 4; mt++)
                        LDSM_X4(af[mt][0], af[mt][1], af[mt][2], af[mt][3],
                                a_ptr[mt] + kk * 32);
#pragma unroll
                    for (int t4 = 0; t4 < 4; t4++) {
                        uint32_t bf0, bf1, bf2, bf3;
                        LDSM_X4(bf0, bf1, bf2, bf3, wb + b_off[t4] + ks * 32);
#pragma unroll
                        for (int mt = 0; mt < 4; mt++) {
                            MMA16816(acc[mt][2 * t4][0], acc[mt][2 * t4][1],
                                     acc[mt][2 * t4][2], acc[mt][2 * t4][3],
                                     af[mt][0], af[mt][1], af[mt][2], af[mt][3],
                                     bf0, bf1);
                            MMA16816(acc[mt][2 * t4 + 1][0], acc[mt][2 * t4 + 1][1],
                                     acc[mt][2 * t4 + 1][2], acc[mt][2 * t4 + 1][3],
                                     af[mt][0], af[mt][1], af[mt][2], af[mt][3],
                                     bf2, bf3);
                        }
                    }
                }
                // restage this buffer with chunk (ci+2) mod 16
                stage_slice_warp(smem_base, ci & 1, (ci + 2) & 15, wid, lane);
                ci++;
            }

            if (L < 3) {
                __syncthreads();   // all warps done reading act for this layer
                // epilogue: act = bf16(relu(D + bias)), in place
#pragma unroll
                for (int mt = 0; mt < 4; mt++) {
                    int r0 = mt * 16 + (lane >> 2);
#pragma unroll
                    for (int nt = 0; nt < 8; nt++) {
                        int c0 = nbase + nt * 8 + (lane & 3) * 2;
                        float bia0 = s_bias[c0], bia1 = s_bias[c0 + 1];
                        float f0 = fmaxf(acc[mt][nt][0] + bia0, 0.0f);
                        float f1 = fmaxf(acc[mt][nt][1] + bia1, 0.0f);
                        float f2 = fmaxf(acc[mt][nt][2] + bia0, 0.0f);
                        float f3 = fmaxf(acc[mt][nt][3] + bia1, 0.0f);
                        uint32_t v01 = (uint32_t)__bfloat16_as_ushort(__float2bfloat16(f0))
                                     | ((uint32_t)__bfloat16_as_ushort(__float2bfloat16(f1)) << 16);
                        uint32_t v23 = (uint32_t)__bfloat16_as_ushort(__float2bfloat16(f2))
                                     | ((uint32_t)__bfloat16_as_ushort(__float2bfloat16(f3)) << 16);
                        *(uint32_t*)(s_act + r0 * ACT_STRIDE_H + c0) = v01;
                        *(uint32_t*)(s_act + (r0 + 8) * ACT_STRIDE_H + c0) = v23;
                    }
                }
                __syncthreads();
            } else {
                // final layer: relu(D + qbias), sum over rows -> s_acc
#pragma unroll
                for (int nt = 0; nt < 8; nt++) {
                    int c0 = nbase + nt * 8 + (lane & 3) * 2;
                    float bia0 = s_bias[c0], bia1 = s_bias[c0 + 1];
                    float cs0 = 0.0f, cs1 = 0.0f;
#pragma unroll
                    for (int mt = 0; mt < 4; mt++) {
                        cs0 += fmaxf(acc[mt][nt][0] + bia0, 0.0f)
                             + fmaxf(acc[mt][nt][2] + bia0, 0.0f);
                        cs1 += fmaxf(acc[mt][nt][1] + bia1, 0.0f)
                             + fmaxf(acc[mt][nt][3] + bia1, 0.0f);
                    }
#pragma unroll
                    for (int s = 4; s < 32; s <<= 1) {
                        cs0 += __shfl_xor_sync(0xFFFFFFFF, cs0, s);
                        cs1 += __shfl_xor_sync(0xFFFFFFFF, cs1, s);
                    }
                    if ((lane >> 2) == 0) {
                        atomicAdd(&s_acc[c0], cs0);
                        atomicAdd(&s_acc[c0 + 1], cs1);
                    }
                }
                __syncthreads();
            }
        }

        atomicAdd(&g_xg[b * 256 + tid], s_acc[tid]);
        atomicAdd(&g_xg[b * 256 + tid + 128], s_acc[tid + 128]);
    }

    CP_ASYNC_WAIT(0);   // drain speculative prefetches

    // ---- fused f-MLP tail: last 64 CTAs each handle one batch ----
    __threadfence();
    if (tid == 0) s_done = atomicAdd(&g_done_ctr, 1);
    __syncthreads();
    int dv = s_done;
    if (dv < GRID_MAIN - NB) return;
    int fb = dv - (GRID_MAIN - NB);     // my batch

    if (tid == 0) {
        while (atomicAdd(&g_done_ctr, 0) < GRID_MAIN) { }
    }
    __syncthreads();
    __threadfence();

    float* s0 = s_acc;      // 256 floats
    float* s1 = s_bias;     // 256 floats
    int w = wid, ln = lane;

    s0[tid] = g_xg[fb * 256 + tid];
    s0[tid + 128] = g_xg[fb * 256 + tid + 128];
    __syncthreads();

#pragma unroll 1
    for (int o = w; o < 256; o += 4) {
        const float* wr = Wf1 + o * 256;
        float s = 0.0f;
#pragma unroll
        for (int k = 0; k < 8; k++) s += wr[ln + 32 * k] * s0[ln + 32 * k];
#pragma unroll
        for (int sh = 16; sh; sh >>= 1) s += __shfl_xor_sync(0xFFFFFFFFu, s, sh);
        if (ln == 0) s1[o] = fmaxf(s + bf1v[o], 0.0f);
    }
    __syncthreads();

#pragma unroll 1
    for (int o = w; o < 256; o += 4) {
        const float* wr = Wf2 + o * 256;
        float s = 0.0f;
#pragma unroll
        for (int k = 0; k < 8; k++) s += wr[ln + 32 * k] * s1[ln + 32 * k];
#pragma unroll
        for (int sh = 16; sh; sh >>= 1) s += __shfl_xor_sync(0xFFFFFFFFu, s, sh);
        if (ln == 0) s0[o] = fmaxf(s + bf2v[o], 0.0f);
    }
    __syncthreads();

#pragma unroll 1
    for (int o = w; o < NOUT; o += 4) {
        const float* wr = Wf3 + o * 256;
        float s = 0.0f;
#pragma unroll
        for (int k = 0; k < 8; k++) s += wr[ln + 32 * k] * s0[ln + 32 * k];
#pragma unroll
        for (int sh = 16; sh; sh >>= 1) s += __shfl_xor_sync(0xFFFFFFFFu, s, sh);
        if (ln == 0) s_lg[o] = s + bf3v[o];
    }
    __syncthreads();
    if (tid == 0) {
        float m = s_lg[0];
        for (int i = 1; i < NOUT; i++) m = fmaxf(m, s_lg[i]);
        float se = 0.0f;
        for (int i = 0; i < NOUT; i++) se += expf(s_lg[i] - m);
        s_lse = m + logf(se);
    }
    __syncthreads();
    if (tid < NOUT) out[fb * NOUT + tid] = s_lg[tid] - s_lse;
}

// ============================================================================
// kernel_launch — 2 launches: prep, main(+fused final)
// ============================================================================
extern "C" void kernel_launch(void* const* d_in, const int* in_sizes, int n_in,
                              void* d_out, int out_size) {
    const float* x    = (const float*)d_in[0];
    const float* qst  = (const float*)d_in[1];
    const float* Wg1  = (const float*)d_in[2];
    const float* bg1  = (const float*)d_in[3];
    const float* Wg2  = (const float*)d_in[4];
    const float* bg2  = (const float*)d_in[5];
    const float* Wg3  = (const float*)d_in[6];
    const float* bg3  = (const float*)d_in[7];
    const float* Wg4  = (const float*)d_in[8];
    const float* bg4  = (const float*)d_in[9];
    const float* Wh1  = (const float*)d_in[10];
    const float* bh1  = (const float*)d_in[11];
    const float* Wf1  = (const float*)d_in[12];
    const float* bf1v = (const float*)d_in[13];
    const float* Wf2  = (const float*)d_in[14];
    const float* bf2v = (const float*)d_in[15];
    const float* Wf3  = (const float*)d_in[16];
    const float* bf3v = (const float*)d_in[17];
    float* out = (float*)d_out;

    cudaFuncSetAttribute(k_main, cudaFuncAttributeMaxDynamicSharedMemorySize,
                         SMEM_MAIN_SZ);
    cudaFuncSetAttribute(k_prep, cudaFuncAttributeMaxDynamicSharedMemorySize,
                         PREP_DSM);

    k_prep<<<1024, 256, PREP_DSM>>>(x, Wg1, qst, Wh1, bh1, Wg2, Wg3, Wg4);
    k_main<<<GRID_MAIN, 128, SMEM_MAIN_SZ>>>(bg1, bg2, bg3, bg4,
                                             Wf1, bf1v, Wf2, bf2v, Wf3, bf3v,
                                             out);
}

// round 15
// speedup vs baseline: 1.0372x; 1.0372x over previous
#include <cuda_runtime.h>
#include <cuda_bf16.h>
#include <cstdint>

// ============================================================================
// Problem constants: B=64, K=24, D=8, n=64 obj, 4096 pairs/batch, IN=52
// ============================================================================
static constexpr int NB   = 64;
static constexpr int NOBJ = 64;
static constexpr int HID  = 256;
static constexpr int NOUT = 28;
static constexpr int NTILES = 4096;   // 64 batches x 64 tiles of 64 rows

// ============================================================================
// PTX helpers: ldmatrix + mma.sync + cp.async (sm_80-era, valid on sm_100)
// ============================================================================
__device__ __forceinline__ uint32_t smem_to_u32(const void* smem_ptr) {
    uint32_t addr;
    asm("{ .reg .u64 tmp; cvta.to.shared.u64 tmp, %1; cvt.u32.u64 %0, tmp; }"
        : "=r"(addr) : "l"(smem_ptr));
    return addr;
}

#define LDSM_X4(r0, r1, r2, r3, addr) \
    asm volatile("ldmatrix.sync.aligned.m8n8.x4.shared.b16 {%0,%1,%2,%3}, [%4];" \
                 : "=r"(r0), "=r"(r1), "=r"(r2), "=r"(r3) : "r"(addr))

#define MMA16816(d0, d1, d2, d3, a0, a1, a2, a3, b0, b1) \
    asm volatile("mma.sync.aligned.m16n8k16.row.col.f32.bf16.bf16.f32 " \
                 "{%0,%1,%2,%3}, {%4,%5,%6,%7}, {%8,%9}, {%0,%1,%2,%3};" \
                 : "+f"(d0), "+f"(d1), "+f"(d2), "+f"(d3) \
                 : "r"(a0), "r"(a1), "r"(a2), "r"(a3), "r"(b0), "r"(b1))

#define CP_ASYNC16(dst_u32, src_ptr) \
    asm volatile("cp.async.cg.shared.global [%0], [%1], 16;" \
                 :: "r"(dst_u32), "l"(src_ptr))

#define CP_ASYNC_COMMIT() asm volatile("cp.async.commit_group;" ::: "memory")
#define CP_ASYNC_WAIT(n)  asm volatile("cp.async.wait_group %0;" :: "n"(n) : "memory")

// ============================================================================
// Device-global scratch (no dynamic allocation allowed)
// ============================================================================
__device__ __align__(16) float g_A[NB * NOBJ * HID];
__device__ __align__(16) float g_C[NB * NOBJ * HID];
__device__ __align__(16) float g_qbias[NB * HID];
__device__ float g_xg[NB * HID];
__device__ int   g_tile_ctr;
// chunked layout: [ci = layer*4 + kchunk][out 0..255][k 0..63] bf16
__device__ __align__(16) __nv_bfloat16 g_Wbf[4 * HID * HID];

// ============================================================================
// K_PREP (1024 blocks, 256 threads):
//  blocks [0,512):    A/C precompute (8 objects/block, coalesced Wg1 staging)
//  blocks [512,768):  qbias (4 blocks per batch, 64 rows each)
//  blocks [768,1024): weight convert fp32->bf16 (4 elems/thread) + zero g_xg
// ============================================================================
static constexpr int PREP_DSM = 2 * 26 * 257 * 4;   // 53456 B

__global__ void k_prep(const float* __restrict__ x,   const float* __restrict__ Wg1,
                       const float* __restrict__ qst, const float* __restrict__ Wh1,
                       const float* __restrict__ bh1, const float* __restrict__ Wg2,
                       const float* __restrict__ Wg3, const float* __restrict__ Wg4) {
    extern __shared__ float dsm[];
    __shared__ float feat[8][26];
    __shared__ float qs[256];
    int bid = blockIdx.x;
    int t   = threadIdx.x;

    if (bid < 512) {
        // ---- A/C precompute: 8 object-groups of 8 per batch ----
        float* s_wA = dsm;                 // [26][257], bank = i+o (conflict-free)
        float* s_wC = dsm + 26 * 257;
        int ab = bid >> 3;
        int jg = bid & 7;

        if (t < 8 * 26) {
            int jj = t / 26, i = t % 26;
            int j = jg * 8 + jj;
            int r = j >> 3, c = j & 7;
            float v;
            if (i < 24)       v = x[((ab * 24 + i) * 8 + r) * 8 + c];
            else if (i == 24) v = c * (8.0f / 7.0f) - 4.0f;
            else              v = r * (8.0f / 7.0f) - 4.0f;
            feat[jj][i] = v;
        }
        // coalesced linear load of Wg1 [256 out x 52 in], high MLP
#pragma unroll 13
        for (int j = t; j < 256 * 52; j += 256) {
            int o = j / 52, i = j % 52;
            float v = Wg1[j];
            if (i < 26) s_wA[i * 257 + o] = v;
            else        s_wC[(i - 26) * 257 + o] = v;
        }
        __syncthreads();

        int o = t;
#pragma unroll
        for (int jj = 0; jj < 8; jj++) {
            float sa = 0.0f, sc = 0.0f;
#pragma unroll
            for (int i = 0; i < 26; i++) {
                float f = feat[jj][i];
                sa += s_wA[i * 257 + o] * f;
                sc += s_wC[i * 257 + o] * f;
            }
            int j = jg * 8 + jj;
            g_A[(ab * NOBJ + j) * HID + o] = sa;
            g_C[(ab * NOBJ + j) * HID + o] = sc;
        }
    } else if (bid < 768) {
        // ---- qbias: 4 blocks per batch, 64 rows each, warp-per-row ----
        int idx = bid - 512;
        int qb = idx >> 2;           // batch
        int og = idx & 3;            // 64-row group
        int w = t >> 5, lane = t & 31;
        qs[t] = qst[qb * 256 + t];
        __syncthreads();
#pragma unroll 1
        for (int oi = 0; oi < 8; oi++) {
            int o = og * 64 + w * 8 + oi;
            const float* wr = Wh1 + o * 512 + 256;
            float s = 0.0f;
#pragma unroll
            for (int k = 0; k < 8; k++) s += wr[lane + 32 * k] * qs[lane + 32 * k];
#pragma unroll
            for (int sh = 16; sh; sh >>= 1) s += __shfl_xor_sync(0xFFFFFFFFu, s, sh);
            if (lane == 0) g_qbias[qb * 256 + o] = s + bh1[o];
        }
    } else {
        // ---- weight convert, 4 elems per thread; also zero g_xg / counter ----
        int base = (bid - 768) * 1024 + t;
#pragma unroll
        for (int k = 0; k < 4; k++) {
            int idx = base + k * 256;
            if (idx == 0) g_tile_ctr = 0;
            if (idx < NB * HID) g_xg[idx] = 0.0f;
            int layer = idx >> 16, e = idx & 65535;
            int o = e >> 8, i = e & 255;
            float v;
            if (layer == 0)      v = Wg2[e];
            else if (layer == 1) v = Wg3[e];
            else if (layer == 2) v = Wg4[e];
            else                 v = Wh1[o * 512 + i];
            int c = i >> 6, kk = i & 63;
            g_Wbf[(((layer * 4 + c) * 256 + o) << 6) + kk] = __float2bfloat16(v);
        }
    }
}

// ============================================================================
// K4: fused RN core, HMMA, persistent CTAs with dynamic tile stealing.
// Grid = 2048 CTAs, 128 threads (4 warps), 64 rows/tile, 2 CTAs/SM.
// ============================================================================
static constexpr int ACT_STRIDE_B = 528;
static constexpr int ACT_STRIDE_H = 264;
static constexpr int WCH_STRIDE_B = 144;
static constexpr int SMEM_ACT  = 0;                             // 64*528 = 33792
static constexpr int SMEM_W0   = 33792;
static constexpr int SMEM_W1   = SMEM_W0 + 256 * WCH_STRIDE_B;  // 70656
static constexpr int SMEM_BIAS = SMEM_W1 + 256 * WCH_STRIDE_B;  // 107520
static constexpr int SMEM_RACC = SMEM_BIAS + 1024;              // 108544
static constexpr int SMEM_MAIN_SZ = SMEM_RACC + 1024;           // 109568

// Stage this warp's 64-row slice (8 KB) of global chunk ci into buffer buf_sel.
__device__ __forceinline__ void stage_slice_warp(uint32_t smem_base, int buf_sel,
                                                 int ci, int wid, int lane) {
    const char* src = (const char*)g_Wbf + (size_t)ci * 32768 + (size_t)wid * 8192;
    uint32_t dstb = smem_base + (buf_sel ? SMEM_W1 : SMEM_W0) + wid * 64 * WCH_STRIDE_B;
#pragma unroll
    for (int i = 0; i < 16; i++) {
        int idx = i * 32 + lane;          // 16B unit, 512 per warp slice
        int row = idx >> 3;               // 8 x 16B per 128B source row
        int col = idx & 7;
        CP_ASYNC16(dstb + row * WCH_STRIDE_B + col * 16, src + idx * 16);
    }
    CP_ASYNC_COMMIT();
}

__global__ void __launch_bounds__(128, 2)
k_main(const float* __restrict__ bg1, const float* __restrict__ bg2,
       const float* __restrict__ bg3, const float* __restrict__ bg4) {
    extern __shared__ char smem[];
    __shared__ int s_tile;
    const uint32_t smem_base = smem_to_u32(smem);

    __nv_bfloat16* s_act = (__nv_bfloat16*)(smem + SMEM_ACT);
    float* s_bias = (float*)(smem + SMEM_BIAS);
    float* s_acc  = (float*)(smem + SMEM_RACC);

    int tid  = threadIdx.x;
    int wid  = tid >> 5;
    int lane = tid & 31;
    int nbase = wid * 64;

    // fragment addresses (tile-invariant)
    uint32_t a_ptr[4];
#pragma unroll
    for (int mt = 0; mt < 4; mt++) {
        int rr = mt * 16 + (lane & 15);
        a_ptr[mt] = smem_base + SMEM_ACT + rr * ACT_STRIDE_B + (lane >> 4) * 16;
    }
    uint32_t b_off[4];
#pragma unroll
    for (int t4 = 0; t4 < 4; t4++) {
        int rr = nbase + t4 * 16 + ((lane >> 4) << 3) + (lane & 7);
        b_off[t4] = rr * WCH_STRIDE_B + ((lane >> 3) & 1) * 16;
    }

    // prologue: prefetch chunks 0 and 1 (this warp's slices)
    stage_slice_warp(smem_base, 0, 0, wid, lane);
    stage_slice_warp(smem_base, 1, 1, wid, lane);

    int ci = 0;   // persistent global chunk counter; ci & 15 = chunk id

#pragma unroll 1
    while (true) {
        if (tid == 0) s_tile = atomicAdd(&g_tile_ctr, 1);
        __syncthreads();
        int tile = s_tile;
        if (tile >= NTILES) break;
        int b    = tile >> 6;
        int row0 = (tile & 63) << 6;

        s_acc[tid] = 0.0f;
        s_acc[tid + 128] = 0.0f;

        // ---- layer 1: act = relu(A[b,q] + C[b,p] + bg1), bf16, 64 rows ----
        {
            int r = tid >> 1;
            int half = tid & 1;
            int rowg = row0 + r;
            int p = rowg >> 6, q = rowg & 63;
            const float2* A2 = (const float2*)(g_A + ((b << 6) + q) * HID + half * 128);
            const float2* C2 = (const float2*)(g_C + ((b << 6) + p) * HID + half * 128);
            const float2* B2 = (const float2*)(bg1 + half * 128);
            uint32_t* dst = (uint32_t*)(s_act + r * ACT_STRIDE_H + half * 128);
#pragma unroll
            for (int c = 0; c < 64; c++) {
                float2 av = A2[c], cv = C2[c], bv = B2[c];
                float f0 = fmaxf(av.x + cv.x + bv.x, 0.0f);
                float f1 = fmaxf(av.y + cv.y + bv.y, 0.0f);
                uint32_t lo = (uint32_t)__bfloat16_as_ushort(__float2bfloat16(f0));
                uint32_t hi = (uint32_t)__bfloat16_as_ushort(__float2bfloat16(f1));
                dst[c] = lo | (hi << 16);
            }
        }
        __syncthreads();

        // ---- layers 2..5: 16 chunks, warp-private double buffering ----
#pragma unroll 1
        for (int L = 0; L < 4; L++) {
            const float* bp = (L == 0) ? bg2 : (L == 1) ? bg3 : (L == 2) ? bg4
                                             : (const float*)(g_qbias + b * 256);
            s_bias[tid] = bp[tid];
            s_bias[tid + 128] = bp[tid + 128];

            float acc[4][8][4];
#pragma unroll
            for (int mt = 0; mt < 4; mt++)
#pragma unroll
                for (int nt = 0; nt < 8; nt++)
#pragma unroll
                    for (int j = 0; j < 4; j++) acc[mt][nt][j] = 0.0f;

#pragma unroll 1
            for (int c = 0; c < 4; c++) {
                CP_ASYNC_WAIT(1);
                __syncwarp();
                uint32_t wb = smem_base + ((ci & 1) ? SMEM_W1 : SMEM_W0);
#pragma unroll
                for (int ks = 0; ks < 4; ks++) {
                    int kk = c * 4 + ks;
                    uint32_t af[4][4];
#pragma unroll
                    for (int mt = 0; mt < 4; mt++)
                        LDSM_X4(af[mt][0], af[mt][1], af[mt][2], af[mt][3],
                                a_ptr[mt] + kk * 32);
#pragma unroll
                    for (int t4 = 0; t4 < 4; t4++) {
                        uint32_t bf0, bf1, bf2, bf3;
                        LDSM_X4(bf0, bf1, bf2, bf3, wb + b_off[t4] + ks * 32);
#pragma unroll
                        for (int mt = 0; mt < 4; mt++) {
                            MMA16816(acc[mt][2 * t4][0], acc[mt][2 * t4][1],
                                     acc[mt][2 * t4][2], acc[mt][2 * t4][3],
                                     af[mt][0], af[mt][1], af[mt][2], af[mt][3],
                                     bf0, bf1);
                            MMA16816(acc[mt][2 * t4 + 1][0], acc[mt][2 * t4 + 1][1],
                                     acc[mt][2 * t4 + 1][2], acc[mt][2 * t4 + 1][3],
                                     af[mt][0], af[mt][1], af[mt][2], af[mt][3],
                                     bf2, bf3);
                        }
                    }
                }
                // restage this buffer with chunk (ci+2) mod 16
                stage_slice_warp(smem_base, ci & 1, (ci + 2) & 15, wid, lane);
                ci++;
            }

            if (L < 3) {
                __syncthreads();   // all warps done reading act for this layer
                // epilogue: act = bf16(relu(D + bias)), in place
#pragma unroll
                for (int mt = 0; mt < 4; mt++) {
                    int r0 = mt * 16 + (lane >> 2);
#pragma unroll
                    for (int nt = 0; nt < 8; nt++) {
                        int c0 = nbase + nt * 8 + (lane & 3) * 2;
                        float bia0 = s_bias[c0], bia1 = s_bias[c0 + 1];
                        float f0 = fmaxf(acc[mt][nt][0] + bia0, 0.0f);
                        float f1 = fmaxf(acc[mt][nt][1] + bia1, 0.0f);
                        float f2 = fmaxf(acc[mt][nt][2] + bia0, 0.0f);
                        float f3 = fmaxf(acc[mt][nt][3] + bia1, 0.0f);
                        uint32_t v01 = (uint32_t)__bfloat16_as_ushort(__float2bfloat16(f0))
                                     | ((uint32_t)__bfloat16_as_ushort(__float2bfloat16(f1)) << 16);
                        uint32_t v23 = (uint32_t)__bfloat16_as_ushort(__float2bfloat16(f2))
                                     | ((uint32_t)__bfloat16_as_ushort(__float2bfloat16(f3)) << 16);
                        *(uint32_t*)(s_act + r0 * ACT_STRIDE_H + c0) = v01;
                        *(uint32_t*)(s_act + (r0 + 8) * ACT_STRIDE_H + c0) = v23;
                    }
                }
                __syncthreads();
            } else {
                // final layer: relu(D + qbias), sum over rows -> s_acc
#pragma unroll
                for (int nt = 0; nt < 8; nt++) {
                    int c0 = nbase + nt * 8 + (lane & 3) * 2;
                    float bia0 = s_bias[c0], bia1 = s_bias[c0 + 1];
                    float cs0 = 0.0f, cs1 = 0.0f;
#pragma unroll
                    for (int mt = 0; mt < 4; mt++) {
                        cs0 += fmaxf(acc[mt][nt][0] + bia0, 0.0f)
                             + fmaxf(acc[mt][nt][2] + bia0, 0.0f);
                        cs1 += fmaxf(acc[mt][nt][1] + bia1, 0.0f)
                             + fmaxf(acc[mt][nt][3] + bia1, 0.0f);
                    }
#pragma unroll
                    for (int s = 4; s < 32; s <<= 1) {
                        cs0 += __shfl_xor_sync(0xFFFFFFFF, cs0, s);
                        cs1 += __shfl_xor_sync(0xFFFFFFFF, cs1, s);
                    }
                    if ((lane >> 2) == 0) {
                        atomicAdd(&s_acc[c0], cs0);
                        atomicAdd(&s_acc[c0 + 1], cs1);
                    }
                }
                __syncthreads();
            }
        }

        atomicAdd(&g_xg[b * 256 + tid], s_acc[tid]);
        atomicAdd(&g_xg[b * 256 + tid + 128], s_acc[tid + 128]);
    }

    CP_ASYNC_WAIT(0);   // drain speculative prefetches before exit
}

// ============================================================================
// K5: f-MLP + log_softmax — warp-per-row coalesced matvecs
// ============================================================================
__global__ void k_final(const float* __restrict__ Wf1, const float* __restrict__ bf1v,
                        const float* __restrict__ Wf2, const float* __restrict__ bf2v,
                        const float* __restrict__ Wf3, const float* __restrict__ bf3v,
                        float* __restrict__ out) {
    __shared__ float s0[256], s1[256], lg[NOUT];
    __shared__ float lse;
    int b = blockIdx.x, t = threadIdx.x;
    int w = t >> 5, lane = t & 31;
    s0[t] = g_xg[b * 256 + t];
    __syncthreads();

#pragma unroll 1
    for (int o = w; o < 256; o += 8) {
        const float* wr = Wf1 + o * 256;
        float s = 0.0f;
#pragma unroll
        for (int k = 0; k < 8; k++) s += wr[lane + 32 * k] * s0[lane + 32 * k];
#pragma unroll
        for (int sh = 16; sh; sh >>= 1) s += __shfl_xor_sync(0xFFFFFFFFu, s, sh);
        if (lane == 0) s1[o] = fmaxf(s + bf1v[o], 0.0f);
    }
    __syncthreads();

#pragma unroll 1
    for (int o = w; o < 256; o += 8) {
        const float* wr = Wf2 + o * 256;
        float s = 0.0f;
#pragma unroll
        for (int k = 0; k < 8; k++) s += wr[lane + 32 * k] * s1[lane + 32 * k];
#pragma unroll
        for (int sh = 16; sh; sh >>= 1) s += __shfl_xor_sync(0xFFFFFFFFu, s, sh);
        if (lane == 0) s0[o] = fmaxf(s + bf2v[o], 0.0f);
    }
    __syncthreads();

#pragma unroll 1
    for (int o = w; o < NOUT; o += 8) {
        const float* wr = Wf3 + o * 256;
        float s = 0.0f;
#pragma unroll
        for (int k = 0; k < 8; k++) s += wr[lane + 32 * k] * s0[lane + 32 * k];
#pragma unroll
        for (int sh = 16; sh; sh >>= 1) s += __shfl_xor_sync(0xFFFFFFFFu, s, sh);
        if (lane == 0) lg[o] = s + bf3v[o];
    }
    __syncthreads();
    if (t == 0) {
        float m = lg[0];
        for (int i = 1; i < NOUT; i++) m = fmaxf(m, lg[i]);
        float se = 0.0f;
        for (int i = 0; i < NOUT; i++) se += expf(lg[i] - m);
        lse = m + logf(se);
    }
    __syncthreads();
    if (t < NOUT) out[b * NOUT + t] = lg[t] - lse;
}

// ============================================================================
// kernel_launch — 3 launches: prep, main, final
// ============================================================================
extern "C" void kernel_launch(void* const* d_in, const int* in_sizes, int n_in,
                              void* d_out, int out_size) {
    const float* x    = (const float*)d_in[0];
    const float* qst  = (const float*)d_in[1];
    const float* Wg1  = (const float*)d_in[2];
    const float* bg1  = (const float*)d_in[3];
    const float* Wg2  = (const float*)d_in[4];
    const float* bg2  = (const float*)d_in[5];
    const float* Wg3  = (const float*)d_in[6];
    const float* bg3  = (const float*)d_in[7];
    const float* Wg4  = (const float*)d_in[8];
    const float* bg4  = (const float*)d_in[9];
    const float* Wh1  = (const float*)d_in[10];
    const float* bh1  = (const float*)d_in[11];
    const float* Wf1  = (const float*)d_in[12];
    const float* bf1v = (const float*)d_in[13];
    const float* Wf2  = (const float*)d_in[14];
    const float* bf2v = (const float*)d_in[15];
    const float* Wf3  = (const float*)d_in[16];
    const float* bf3v = (const float*)d_in[17];
    float* out = (float*)d_out;

    cudaFuncSetAttribute(k_main, cudaFuncAttributeMaxDynamicSharedMemorySize,
                         SMEM_MAIN_SZ);
    cudaFuncSetAttribute(k_prep, cudaFuncAttributeMaxDynamicSharedMemorySize,
                         PREP_DSM);

    k_prep<<<1024, 256, PREP_DSM>>>(x, Wg1, qst, Wh1, bh1, Wg2, Wg3, Wg4);
    k_main<<<2048, 128, SMEM_MAIN_SZ>>>(bg1, bg2, bg3, bg4);
    k_final<<<NB, 256>>>(Wf1, bf1v, Wf2, bf2v, Wf3, bf3v, out);
}

// round 16
// speedup vs baseline: 1.0373x; 1.0001x over previous
#include <cuda_runtime.h>
#include <cuda_bf16.h>
#include <cstdint>

// ============================================================================
// Problem constants: B=64, K=24, D=8, n=64 obj, 4096 pairs/batch, IN=52
// ============================================================================
static constexpr int NB   = 64;
static constexpr int NOBJ = 64;
static constexpr int HID  = 256;
static constexpr int NOUT = 28;
static constexpr int NTILES = 4096;   // 64 batches x 64 tiles of 64 rows

// ============================================================================
// PTX helpers: ldmatrix + mma.sync + cp.async (sm_80-era, valid on sm_100)
// ============================================================================
__device__ __forceinline__ uint32_t smem_to_u32(const void* smem_ptr) {
    uint32_t addr;
    asm("{ .reg .u64 tmp; cvta.to.shared.u64 tmp, %1; cvt.u32.u64 %0, tmp; }"
        : "=r"(addr) : "l"(smem_ptr));
    return addr;
}

#define LDSM_X4(r0, r1, r2, r3, addr) \
    asm volatile("ldmatrix.sync.aligned.m8n8.x4.shared.b16 {%0,%1,%2,%3}, [%4];" \
                 : "=r"(r0), "=r"(r1), "=r"(r2), "=r"(r3) : "r"(addr))

#define MMA16816(d0, d1, d2, d3, a0, a1, a2, a3, b0, b1) \
    asm volatile("mma.sync.aligned.m16n8k16.row.col.f32.bf16.bf16.f32 " \
                 "{%0,%1,%2,%3}, {%4,%5,%6,%7}, {%8,%9}, {%0,%1,%2,%3};" \
                 : "+f"(d0), "+f"(d1), "+f"(d2), "+f"(d3) \
                 : "r"(a0), "r"(a1), "r"(a2), "r"(a3), "r"(b0), "r"(b1))

#define CP_ASYNC16(dst_u32, src_ptr) \
    asm volatile("cp.async.cg.shared.global [%0], [%1], 16;" \
                 :: "r"(dst_u32), "l"(src_ptr))

#define CP_ASYNC_COMMIT() asm volatile("cp.async.commit_group;" ::: "memory")
#define CP_ASYNC_WAIT(n)  asm volatile("cp.async.wait_group %0;" :: "n"(n) : "memory")

// ============================================================================
// Device-global scratch (no dynamic allocation allowed)
// ============================================================================
__device__ __align__(16) float g_A[NB * NOBJ * HID];
__device__ __align__(16) float g_C[NB * NOBJ * HID];
__device__ __align__(16) float g_qbias[NB * HID];
__device__ float g_xg[NB * HID];
__device__ int   g_tile_ctr;
// chunked layout: [ci = layer*4 + kchunk][out 0..255][k 0..63] bf16
__device__ __align__(16) __nv_bfloat16 g_Wbf[4 * HID * HID];

// ============================================================================
// K_PREP (1024 blocks, 256 threads):
//  blocks [0,512):    A/C precompute (8 objects/block, coalesced Wg1 staging)
//  blocks [512,768):  qbias (4 blocks per batch, 64 rows each)
//  blocks [768,1024): weight convert fp32->bf16 (4 elems/thread) + zero g_xg
// ============================================================================
static constexpr int PREP_DSM = 2 * 26 * 257 * 4;   // 53456 B

__global__ void k_prep(const float* __restrict__ x,   const float* __restrict__ Wg1,
                       const float* __restrict__ qst, const float* __restrict__ Wh1,
                       const float* __restrict__ bh1, const float* __restrict__ Wg2,
                       const float* __restrict__ Wg3, const float* __restrict__ Wg4) {
    extern __shared__ float dsm[];
    __shared__ float feat[8][26];
    __shared__ float qs[256];
    int bid = blockIdx.x;
    int t   = threadIdx.x;

    if (bid < 512) {
        // ---- A/C precompute: 8 object-groups of 8 per batch ----
        float* s_wA = dsm;                 // [26][257], bank = i+o (conflict-free)
        float* s_wC = dsm + 26 * 257;
        int ab = bid >> 3;
        int jg = bid & 7;

        if (t < 8 * 26) {
            int jj = t / 26, i = t % 26;
            int j = jg * 8 + jj;
            int r = j >> 3, c = j & 7;
            float v;
            if (i < 24)       v = x[((ab * 24 + i) * 8 + r) * 8 + c];
            else if (i == 24) v = c * (8.0f / 7.0f) - 4.0f;
            else              v = r * (8.0f / 7.0f) - 4.0f;
            feat[jj][i] = v;
        }
        // coalesced linear load of Wg1 [256 out x 52 in], high MLP
#pragma unroll 13
        for (int j = t; j < 256 * 52; j += 256) {
            int o = j / 52, i = j % 52;
            float v = Wg1[j];
            if (i < 26) s_wA[i * 257 + o] = v;
            else        s_wC[(i - 26) * 257 + o] = v;
        }
        __syncthreads();

        int o = t;
#pragma unroll
        for (int jj = 0; jj < 8; jj++) {
            float sa = 0.0f, sc = 0.0f;
#pragma unroll
            for (int i = 0; i < 26; i++) {
                float f = feat[jj][i];
                sa += s_wA[i * 257 + o] * f;
                sc += s_wC[i * 257 + o] * f;
            }
            int j = jg * 8 + jj;
            g_A[(ab * NOBJ + j) * HID + o] = sa;
            g_C[(ab * NOBJ + j) * HID + o] = sc;
        }
    } else if (bid < 768) {
        // ---- qbias: 4 blocks per batch, 64 rows each, warp-per-row ----
        int idx = bid - 512;
        int qb = idx >> 2;           // batch
        int og = idx & 3;            // 64-row group
        int w = t >> 5, lane = t & 31;
        qs[t] = qst[qb * 256 + t];
        __syncthreads();
#pragma unroll 1
        for (int oi = 0; oi < 8; oi++) {
            int o = og * 64 + w * 8 + oi;
            const float* wr = Wh1 + o * 512 + 256;
            float s = 0.0f;
#pragma unroll
            for (int k = 0; k < 8; k++) s += wr[lane + 32 * k] * qs[lane + 32 * k];
#pragma unroll
            for (int sh = 16; sh; sh >>= 1) s += __shfl_xor_sync(0xFFFFFFFFu, s, sh);
            if (lane == 0) g_qbias[qb * 256 + o] = s + bh1[o];
        }
    } else {
        // ---- weight convert, 4 elems per thread; also zero g_xg / counter ----
        int base = (bid - 768) * 1024 + t;
#pragma unroll
        for (int k = 0; k < 4; k++) {
            int idx = base + k * 256;
            if (idx == 0) g_tile_ctr = 0;
            if (idx < NB * HID) g_xg[idx] = 0.0f;
            int layer = idx >> 16, e = idx & 65535;
            int o = e >> 8, i = e & 255;
            float v;
            if (layer == 0)      v = Wg2[e];
            else if (layer == 1) v = Wg3[e];
            else if (layer == 2) v = Wg4[e];
            else                 v = Wh1[o * 512 + i];
            int c = i >> 6, kk = i & 63;
            g_Wbf[(((layer * 4 + c) * 256 + o) << 6) + kk] = __float2bfloat16(v);
        }
    }
}

// ============================================================================
// K4: fused RN core, HMMA, persistent CTAs with dynamic tile stealing.
// Grid = 2048 CTAs, 128 threads (4 warps), 64 rows/tile, 2 CTAs/SM.
// ============================================================================
static constexpr int ACT_STRIDE_B = 528;
static constexpr int ACT_STRIDE_H = 264;
static constexpr int WCH_STRIDE_B = 144;
static constexpr int SMEM_ACT  = 0;                             // 64*528 = 33792
static constexpr int SMEM_W0   = 33792;
static constexpr int SMEM_W1   = SMEM_W0 + 256 * WCH_STRIDE_B;  // 70656
static constexpr int SMEM_BIAS = SMEM_W1 + 256 * WCH_STRIDE_B;  // 107520
static constexpr int SMEM_RACC = SMEM_BIAS + 1024;              // 108544
static constexpr int SMEM_MAIN_SZ = SMEM_RACC + 1024;           // 109568

// Stage this warp's 64-row slice (8 KB) of global chunk ci into buffer buf_sel.
__device__ __forceinline__ void stage_slice_warp(uint32_t smem_base, int buf_sel,
                                                 int ci, int wid, int lane) {
    const char* src = (const char*)g_Wbf + (size_t)ci * 32768 + (size_t)wid * 8192;
    uint32_t dstb = smem_base + (buf_sel ? SMEM_W1 : SMEM_W0) + wid * 64 * WCH_STRIDE_B;
#pragma unroll
    for (int i = 0; i < 16; i++) {
        int idx = i * 32 + lane;          // 16B unit, 512 per warp slice
        int row = idx >> 3;               // 8 x 16B per 128B source row
        int col = idx & 7;
        CP_ASYNC16(dstb + row * WCH_STRIDE_B + col * 16, src + idx * 16);
    }
    CP_ASYNC_COMMIT();
}

__global__ void __launch_bounds__(128, 2)
k_main(const float* __restrict__ bg1, const float* __restrict__ bg2,
       const float* __restrict__ bg3, const float* __restrict__ bg4) {
    extern __shared__ char smem[];
    __shared__ int s_tile;
    const uint32_t smem_base = smem_to_u32(smem);

    __nv_bfloat16* s_act = (__nv_bfloat16*)(smem + SMEM_ACT);
    float* s_bias = (float*)(smem + SMEM_BIAS);
    float* s_acc  = (float*)(smem + SMEM_RACC);

    int tid  = threadIdx.x;
    int wid  = tid >> 5;
    int lane = tid & 31;
    int nbase = wid * 64;

    // fragment addresses (tile-invariant)
    uint32_t a_ptr[4];
#pragma unroll
    for (int mt = 0; mt < 4; mt++) {
        int rr = mt * 16 + (lane & 15);
        a_ptr[mt] = smem_base + SMEM_ACT + rr * ACT_STRIDE_B + (lane >> 4) * 16;
    }
    uint32_t b_off[4];
#pragma unroll
    for (int t4 = 0; t4 < 4; t4++) {
        int rr = nbase + t4 * 16 + ((lane >> 4) << 3) + (lane & 7);
        b_off[t4] = rr * WCH_STRIDE_B + ((lane >> 3) & 1) * 16;
    }

    // prologue: prefetch chunks 0 and 1 (this warp's slices)
    stage_slice_warp(smem_base, 0, 0, wid, lane);
    stage_slice_warp(smem_base, 1, 1, wid, lane);

    int ci = 0;   // persistent global chunk counter; ci & 15 = chunk id

#pragma unroll 1
    while (true) {
        if (tid == 0) s_tile = atomicAdd(&g_tile_ctr, 1);
        __syncthreads();
        int tile = s_tile;
        if (tile >= NTILES) break;
        int b    = tile >> 6;
        int row0 = (tile & 63) << 6;

        s_acc[tid] = 0.0f;
        s_acc[tid + 128] = 0.0f;

        // ---- layer 1: act = relu(A[b,q] + C[b,p] + bg1), bf16, 64 rows ----
        {
            int r = tid >> 1;
            int half = tid & 1;
            int rowg = row0 + r;
            int p = rowg >> 6, q = rowg & 63;
            const float2* A2 = (const float2*)(g_A + ((b << 6) + q) * HID + half * 128);
            const float2* C2 = (const float2*)(g_C + ((b << 6) + p) * HID + half * 128);
            const float2* B2 = (const float2*)(bg1 + half * 128);
            uint32_t* dst = (uint32_t*)(s_act + r * ACT_STRIDE_H + half * 128);
#pragma unroll
            for (int c = 0; c < 64; c++) {
                float2 av = A2[c], cv = C2[c], bv = B2[c];
                float f0 = fmaxf(av.x + cv.x + bv.x, 0.0f);
                float f1 = fmaxf(av.y + cv.y + bv.y, 0.0f);
                uint32_t lo = (uint32_t)__bfloat16_as_ushort(__float2bfloat16(f0));
                uint32_t hi = (uint32_t)__bfloat16_as_ushort(__float2bfloat16(f1));
                dst[c] = lo | (hi << 16);
            }
        }
        __syncthreads();

        // ---- layers 2..5: 16 chunks, warp-private double buffering ----
#pragma unroll 1
        for (int L = 0; L < 4; L++) {
            const float* bp = (L == 0) ? bg2 : (L == 1) ? bg3 : (L == 2) ? bg4
                                             : (const float*)(g_qbias + b * 256);
            s_bias[tid] = bp[tid];
            s_bias[tid + 128] = bp[tid + 128];

            float acc[4][8][4];
#pragma unroll
            for (int mt = 0; mt < 4; mt++)
#pragma unroll
                for (int nt = 0; nt < 8; nt++)
#pragma unroll
                    for (int j = 0; j < 4; j++) acc[mt][nt][j] = 0.0f;

#pragma unroll 1
            for (int c = 0; c < 4; c++) {
                CP_ASYNC_WAIT(1);
                __syncwarp();
                uint32_t wb = smem_base + ((ci & 1) ? SMEM_W1 : SMEM_W0);
#pragma unroll
                for (int ks = 0; ks < 4; ks++) {
                    int kk = c * 4 + ks;
                    uint32_t af[4][4];
#pragma unroll
                    for (int mt = 0; mt < 4; mt++)
                        LDSM_X4(af[mt][0], af[mt][1], af[mt][2], af[mt][3],
                                a_ptr[mt] + kk * 32);
#pragma unroll
                    for (int t4 = 0; t4 < 4; t4++) {
                        uint32_t bf0, bf1, bf2, bf3;
                        LDSM_X4(bf0, bf1, bf2, bf3, wb + b_off[t4] + ks * 32);
#pragma unroll
                        for (int mt = 0; mt < 4; mt++) {
                            MMA16816(acc[mt][2 * t4][0], acc[mt][2 * t4][1],
                                     acc[mt][2 * t4][2], acc[mt][2 * t4][3],
                                     af[mt][0], af[mt][1], af[mt][2], af[mt][3],
                                     bf0, bf1);
                            MMA16816(acc[mt][2 * t4 + 1][0], acc[mt][2 * t4 + 1][1],
                                     acc[mt][2 * t4 + 1][2], acc[mt][2 * t4 + 1][3],
                                     af[mt][0], af[mt][1], af[mt][2], af[mt][3],
                                     bf2, bf3);
                        }
                    }
                }
                // restage this buffer with chunk (ci+2) mod 16
                stage_slice_warp(smem_base, ci & 1, (ci + 2) & 15, wid, lane);
                ci++;
            }

            if (L < 3) {
                __syncthreads();   // all warps done reading act for this layer
                // epilogue: act = bf16(relu(D + bias)), in place
#pragma unroll
                for (int mt = 0; mt < 4; mt++) {
                    int r0 = mt * 16 + (lane >> 2);
#pragma unroll
                    for (int nt = 0; nt < 8; nt++) {
                        int c0 = nbase + nt * 8 + (lane & 3) * 2;
                        float bia0 = s_bias[c0], bia1 = s_bias[c0 + 1];
                        float f0 = fmaxf(acc[mt][nt][0] + bia0, 0.0f);
                        float f1 = fmaxf(acc[mt][nt][1] + bia1, 0.0f);
                        float f2 = fmaxf(acc[mt][nt][2] + bia0, 0.0f);
                        float f3 = fmaxf(acc[mt][nt][3] + bia1, 0.0f);
                        uint32_t v01 = (uint32_t)__bfloat16_as_ushort(__float2bfloat16(f0))
                                     | ((uint32_t)__bfloat16_as_ushort(__float2bfloat16(f1)) << 16);
                        uint32_t v23 = (uint32_t)__bfloat16_as_ushort(__float2bfloat16(f2))
                                     | ((uint32_t)__bfloat16_as_ushort(__float2bfloat16(f3)) << 16);
                        *(uint32_t*)(s_act + r0 * ACT_STRIDE_H + c0) = v01;
                        *(uint32_t*)(s_act + (r0 + 8) * ACT_STRIDE_H + c0) = v23;
                    }
                }
                __syncthreads();
            } else {
                // final layer: relu(D + qbias), sum over rows -> s_acc
#pragma unroll
                for (int nt = 0; nt < 8; nt++) {
                    int c0 = nbase + nt * 8 + (lane & 3) * 2;
                    float bia0 = s_bias[c0], bia1 = s_bias[c0 + 1];
                    float cs0 = 0.0f, cs1 = 0.0f;
#pragma unroll
                    for (int mt = 0; mt < 4; mt++) {
                        cs0 += fmaxf(acc[mt][nt][0] + bia0, 0.0f)
                             + fmaxf(acc[mt][nt][2] + bia0, 0.0f);
                        cs1 += fmaxf(acc[mt][nt][1] + bia1, 0.0f)
                             + fmaxf(acc[mt][nt][3] + bia1, 0.0f);
                    }
#pragma unroll
                    for (int s = 4; s < 32; s <<= 1) {
                        cs0 += __shfl_xor_sync(0xFFFFFFFF, cs0, s);
                        cs1 += __shfl_xor_sync(0xFFFFFFFF, cs1, s);
                    }
                    if ((lane >> 2) == 0) {
                        atomicAdd(&s_acc[c0], cs0);
                        atomicAdd(&s_acc[c0 + 1], cs1);
                    }
                }
                __syncthreads();
            }
        }

        atomicAdd(&g_xg[b * 256 + tid], s_acc[tid]);
        atomicAdd(&g_xg[b * 256 + tid + 128], s_acc[tid + 128]);
    }

    CP_ASYNC_WAIT(0);   // drain speculative prefetches before exit
}

// ============================================================================
// K5: f-MLP + log_softmax — warp-per-row coalesced matvecs
// ============================================================================
__global__ void k_final(const float* __restrict__ Wf1, const float* __restrict__ bf1v,
                        const float* __restrict__ Wf2, const float* __restrict__ bf2v,
                        const float* __restrict__ Wf3, const float* __restrict__ bf3v,
                        float* __restrict__ out) {
    __shared__ float s0[256], s1[256], lg[NOUT];
    __shared__ float lse;
    int b = blockIdx.x, t = threadIdx.x;
    int w = t >> 5, lane = t & 31;
    s0[t] = g_xg[b * 256 + t];
    __syncthreads();

#pragma unroll 1
    for (int o = w; o < 256; o += 8) {
        const float* wr = Wf1 + o * 256;
        float s = 0.0f;
#pragma unroll
        for (int k = 0; k < 8; k++) s += wr[lane + 32 * k] * s0[lane + 32 * k];
#pragma unroll
        for (int sh = 16; sh; sh >>= 1) s += __shfl_xor_sync(0xFFFFFFFFu, s, sh);
        if (lane == 0) s1[o] = fmaxf(s + bf1v[o], 0.0f);
    }
    __syncthreads();

#pragma unroll 1
    for (int o = w; o < 256; o += 8) {
        const float* wr = Wf2 + o * 256;
        float s = 0.0f;
#pragma unroll
        for (int k = 0; k < 8; k++) s += wr[lane + 32 * k] * s1[lane + 32 * k];
#pragma unroll
        for (int sh = 16; sh; sh >>= 1) s += __shfl_xor_sync(0xFFFFFFFFu, s, sh);
        if (lane == 0) s0[o] = fmaxf(s + bf2v[o], 0.0f);
    }
    __syncthreads();

#pragma unroll 1
    for (int o = w; o < NOUT; o += 8) {
        const float* wr = Wf3 + o * 256;
        float s = 0.0f;
#pragma unroll
        for (int k = 0; k < 8; k++) s += wr[lane + 32 * k] * s0[lane + 32 * k];
#pragma unroll
        for (int sh = 16; sh; sh >>= 1) s += __shfl_xor_sync(0xFFFFFFFFu, s, sh);
        if (lane == 0) lg[o] = s + bf3v[o];
    }
    __syncthreads();
    if (t == 0) {
        float m = lg[0];
        for (int i = 1; i < NOUT; i++) m = fmaxf(m, lg[i]);
        float se = 0.0f;
        for (int i = 0; i < NOUT; i++) se += expf(lg[i] - m);
        lse = m + logf(se);
    }
    __syncthreads();
    if (t < NOUT) out[b * NOUT + t] = lg[t] - lse;
}

// ============================================================================
// kernel_launch — 3 launches: prep, main, final
// ============================================================================
extern "C" void kernel_launch(void* const* d_in, const int* in_sizes, int n_in,
                              void* d_out, int out_size) {
    const float* x    = (const float*)d_in[0];
    const float* qst  = (const float*)d_in[1];
    const float* Wg1  = (const float*)d_in[2];
    const float* bg1  = (const float*)d_in[3];
    const float* Wg2  = (const float*)d_in[4];
    const float* bg2  = (const float*)d_in[5];
    const float* Wg3  = (const float*)d_in[6];
    const float* bg3  = (const float*)d_in[7];
    const float* Wg4  = (const float*)d_in[8];
    const float* bg4  = (const float*)d_in[9];
    const float* Wh1  = (const float*)d_in[10];
    const float* bh1  = (const float*)d_in[11];
    const float* Wf1  = (const float*)d_in[12];
    const float* bf1v = (const float*)d_in[13];
    const float* Wf2  = (const float*)d_in[14];
    const float* bf2v = (const float*)d_in[15];
    const float* Wf3  = (const float*)d_in[16];
    const float* bf3v = (const float*)d_in[17];
    float* out = (float*)d_out;

    cudaFuncSetAttribute(k_main, cudaFuncAttributeMaxDynamicSharedMemorySize,
                         SMEM_MAIN_SZ);
    cudaFuncSetAttribute(k_prep, cudaFuncAttributeMaxDynamicSharedMemorySize,
                         PREP_DSM);

    k_prep<<<1024, 256, PREP_DSM>>>(x, Wg1, qst, Wh1, bh1, Wg2, Wg3, Wg4);
    k_main<<<2048, 128, SMEM_MAIN_SZ>>>(bg1, bg2, bg3, bg4);
    k_final<<<NB, 256>>>(Wf1, bf1v, Wf2, bf2v, Wf3, bf3v, out);
}